// round 7
// baseline (speedup 1.0000x reference)
#include <cuda_runtime.h>
#include <math.h>

#define Bb 8
#define Tt 2048
#define Ee 1024
#define Hd 128
#define NROW (Bb * Tt)

// Scratch for Q, K, V (8 MB each) — __device__ globals per allocation rules.
__device__ float g_Q[NROW * Hd];
__device__ float g_K[NROW * Hd];
__device__ float g_V[NROW * Hd];

// ---------------------------------------------------------------------------
// Kernel 1: QKV projection. C[16384,128] = X[16384,1024] @ W[1024,128], x3.
// (unchanged — measured ~85% of fp32 peak)
// ---------------------------------------------------------------------------
__global__ __launch_bounds__(256, 2) void qkv_kernel(
    const float* __restrict__ x,
    const float* __restrict__ Wq,
    const float* __restrict__ Wk,
    const float* __restrict__ Wv)
{
    __shared__ float As[2][8][128];  // [buf][k][row]
    __shared__ float Bs[2][8][128];  // [buf][k][col]

    const int which = blockIdx.y;
    const float* __restrict__ W = (which == 0) ? Wq : ((which == 1) ? Wk : Wv);
    float* __restrict__ out = (which == 0) ? g_Q : ((which == 1) ? g_K : g_V);

    const int tid = threadIdx.x;
    const int tx = tid & 15;
    const int ty = tid >> 4;
    const int m0 = blockIdx.x * 128;

    const int arow = tid >> 1;
    const int acol = (tid & 1) * 4;
    const int brow = tid >> 5;
    const int bcol = (tid & 31) * 4;

    const float* xg = x + (size_t)(m0 + arow) * Ee + acol;
    const float* wg = W + (size_t)brow * Hd + bcol;

    float acc[8][8];
#pragma unroll
    for (int i = 0; i < 8; ++i)
#pragma unroll
        for (int j = 0; j < 8; ++j) acc[i][j] = 0.0f;

    {
        float4 a = *(const float4*)xg;
        float4 bv = *(const float4*)wg;
        As[0][acol + 0][arow] = a.x;
        As[0][acol + 1][arow] = a.y;
        As[0][acol + 2][arow] = a.z;
        As[0][acol + 3][arow] = a.w;
        *(float4*)&Bs[0][brow][bcol] = bv;
    }
    __syncthreads();

    int buf = 0;
    const int NT = Ee / 8;
    for (int t = 0; t < NT; ++t) {
        float4 a2, b2;
        if (t < NT - 1) {
            a2 = *(const float4*)(xg + (size_t)(t + 1) * 8);
            b2 = *(const float4*)(wg + (size_t)(t + 1) * 8 * Hd);
        }
#pragma unroll
        for (int k = 0; k < 8; ++k) {
            float4 a0 = *(const float4*)&As[buf][k][ty * 4];
            float4 a1 = *(const float4*)&As[buf][k][64 + ty * 4];
            float4 b0 = *(const float4*)&Bs[buf][k][tx * 4];
            float4 b1 = *(const float4*)&Bs[buf][k][64 + tx * 4];
            float af[8] = {a0.x, a0.y, a0.z, a0.w, a1.x, a1.y, a1.z, a1.w};
            float bf[8] = {b0.x, b0.y, b0.z, b0.w, b1.x, b1.y, b1.z, b1.w};
#pragma unroll
            for (int i = 0; i < 8; ++i)
#pragma unroll
                for (int j = 0; j < 8; ++j)
                    acc[i][j] = fmaf(af[i], bf[j], acc[i][j]);
        }
        if (t < NT - 1) {
            buf ^= 1;
            As[buf][acol + 0][arow] = a2.x;
            As[buf][acol + 1][arow] = a2.y;
            As[buf][acol + 2][arow] = a2.z;
            As[buf][acol + 3][arow] = a2.w;
            *(float4*)&Bs[buf][brow][bcol] = b2;
        }
        __syncthreads();
    }

#pragma unroll
    for (int ih = 0; ih < 2; ++ih) {
#pragma unroll
        for (int i = 0; i < 4; ++i) {
            int row = m0 + ih * 64 + ty * 4 + i;
            float* op = out + (size_t)row * Hd;
            int ii = ih * 4 + i;
            float4 v0 = make_float4(acc[ii][0], acc[ii][1], acc[ii][2], acc[ii][3]);
            float4 v1 = make_float4(acc[ii][4], acc[ii][5], acc[ii][6], acc[ii][7]);
            *(float4*)&op[tx * 4] = v0;
            *(float4*)&op[64 + tx * 4] = v1;
        }
    }
}

// ---------------------------------------------------------------------------
// Kernel 2: flash attention, causal, fp32, scale = sqrt(2048).
// BQ=64, BK=128, 256 threads (16x16). Microtile 4q x 8k (S) / 4q x 8h (PV).
// Thread (tx,ty): q rows = ty*4+i, k/h cols = {tx*4+j, 64+tx*4+j}.
// K and P tiles use a float4-chunk XOR swizzle (chunk ^ ((row>>2)&7)) so the
// transpose-free coalesced stores AND the strided row-reads are conflict-free.
// Blocks pair q-tiles (x, 31-x): every block has exactly 17 k-tile units.
// ---------------------------------------------------------------------------
#define ATTN_SMEM_FLOATS (64*128 /*Qs*/ + 128*128 /*Ks*/ + 128*128 /*Vs*/ + 128*64 /*Ps*/)
#define ATTN_SMEM_BYTES (ATTN_SMEM_FLOATS * 4)

__global__ __launch_bounds__(256, 1) void attn_kernel(float* __restrict__ out)
{
    extern __shared__ float sm[];
    float* Qs = sm;                    // [64 q][128 h]   plain
    float* Ks = sm + 64 * 128;         // [128 k][128 h]  chunk-swizzled
    float* Vs = Ks + 128 * 128;        // [128 k][128 h]  plain
    float* Ps = Vs + 128 * 128;        // [128 k][64 q]   chunk-swizzled

    const int tid = threadIdx.x;
    const int tx = tid & 15;
    const int ty = tid >> 4;
    const int xk = tx & 7;             // swizzle key for this thread's k-rows
    const int b = blockIdx.y;
    const float scale = 45.25483399593904f;  // sqrt(2048)

    for (int half = 0; half < 2; ++half) {
        const int qt = half ? (31 - (int)blockIdx.x) : (int)blockIdx.x;

        __syncthreads();  // smem reuse across halves

        // ---- load Q tile [64][128], plain, float4 coalesced ----
        {
            const float* Qg = g_Q + ((size_t)(b * Tt) + qt * 64) * Hd;
#pragma unroll
            for (int it = 0; it < 8; ++it) {
                int fid = it * 256 + tid;
                int r = fid >> 5;
                int c = (fid & 31) << 2;
                *(float4*)&Qs[r * 128 + c] = *(const float4*)&Qg[(size_t)r * 128 + c];
            }
        }

        float m_i[4], l_i[4], o[4][8];
#pragma unroll
        for (int i = 0; i < 4; ++i) {
            m_i[i] = -INFINITY;
            l_i[i] = 0.0f;
#pragma unroll
            for (int j = 0; j < 8; ++j) o[i][j] = 0.0f;
        }

        const int ktmax = qt >> 1;
        for (int kt = 0; kt <= ktmax; ++kt) {
            __syncthreads();  // prev PV done (Ps, Vs free), Ks free

            // ---- load K (swizzled) and V (plain) tiles ----
            {
                const float* Kg = g_K + ((size_t)(b * Tt) + kt * 128) * Hd;
                const float* Vg = g_V + ((size_t)(b * Tt) + kt * 128) * Hd;
#pragma unroll
                for (int it = 0; it < 16; ++it) {
                    int fid = it * 256 + tid;
                    int r = fid >> 5;          // key row
                    int c = fid & 31;          // float4 chunk in row
                    float4 kval = *(const float4*)&Kg[(size_t)r * 128 + (c << 2)];
                    float4 vval = *(const float4*)&Vg[(size_t)r * 128 + (c << 2)];
                    int cs = (c ^ ((r >> 2) & 7)) << 2;
                    *(float4*)&Ks[r * 128 + cs] = kval;
                    *(float4*)&Vs[r * 128 + (c << 2)] = vval;
                }
            }
            __syncthreads();

            // ---- S = Q K^T, dot-product form over h-chunks ----
            float s[4][8];
#pragma unroll
            for (int i = 0; i < 4; ++i)
#pragma unroll
                for (int j = 0; j < 8; ++j) s[i][j] = 0.0f;

#pragma unroll 2
            for (int hc = 0; hc < 32; ++hc) {
                float4 qv[4], kv[8];
#pragma unroll
                for (int i = 0; i < 4; ++i)
                    qv[i] = *(const float4*)&Qs[(ty * 4 + i) * 128 + (hc << 2)];
                const int pc = ((hc ^ xk) << 2);
#pragma unroll
                for (int j = 0; j < 4; ++j) {
                    kv[j]     = *(const float4*)&Ks[(tx * 4 + j) * 128 + pc];
                    kv[4 + j] = *(const float4*)&Ks[(64 + tx * 4 + j) * 128 + pc];
                }
#pragma unroll
                for (int i = 0; i < 4; ++i)
#pragma unroll
                    for (int j = 0; j < 8; ++j) {
                        s[i][j] = fmaf(qv[i].x, kv[j].x, s[i][j]);
                        s[i][j] = fmaf(qv[i].y, kv[j].y, s[i][j]);
                        s[i][j] = fmaf(qv[i].z, kv[j].z, s[i][j]);
                        s[i][j] = fmaf(qv[i].w, kv[j].w, s[i][j]);
                    }
            }

            // ---- scale + causal mask (only diagonal tile) ----
            if (kt == ktmax) {
#pragma unroll
                for (int i = 0; i < 4; ++i) {
                    int q = qt * 64 + ty * 4 + i;
#pragma unroll
                    for (int j = 0; j < 8; ++j) {
                        int kcol = (j < 4) ? (tx * 4 + j) : (64 + tx * 4 + (j - 4));
                        int kglb = kt * 128 + kcol;
                        s[i][j] = (kglb <= q) ? s[i][j] * scale : -INFINITY;
                    }
                }
            } else {
#pragma unroll
                for (int i = 0; i < 4; ++i)
#pragma unroll
                    for (int j = 0; j < 8; ++j) s[i][j] *= scale;
            }

            // ---- online softmax (row reductions over 16 tx lanes) ----
            float p[4][8];
#pragma unroll
            for (int i = 0; i < 4; ++i) {
                float mt = s[i][0];
#pragma unroll
                for (int j = 1; j < 8; ++j) mt = fmaxf(mt, s[i][j]);
#pragma unroll
                for (int off = 8; off > 0; off >>= 1)
                    mt = fmaxf(mt, __shfl_xor_sync(0xffffffffu, mt, off));
                float m_new = fmaxf(m_i[i], mt);
                float alpha = __expf(m_i[i] - m_new);
                float ls = 0.0f;
#pragma unroll
                for (int j = 0; j < 8; ++j) {
                    p[i][j] = __expf(s[i][j] - m_new);
                    ls += p[i][j];
                }
#pragma unroll
                for (int off = 8; off > 0; off >>= 1)
                    ls += __shfl_xor_sync(0xffffffffu, ls, off);
                l_i[i] = l_i[i] * alpha + ls;
                m_i[i] = m_new;
#pragma unroll
                for (int jj = 0; jj < 8; ++jj) o[i][jj] *= alpha;
            }

            // ---- store P transposed [k][q], chunk-swizzled, float4 ----
            {
                const int qoff = (ty ^ xk) << 2;
#pragma unroll
                for (int j = 0; j < 8; ++j) {
                    int kcol = (j < 4) ? (tx * 4 + j) : (64 + tx * 4 + (j - 4));
                    float4 pv = make_float4(p[0][j], p[1][j], p[2][j], p[3][j]);
                    *(float4*)&Ps[kcol * 64 + qoff] = pv;
                }
            }
            __syncthreads();

            // ---- O += P V ----
#pragma unroll 4
            for (int kk = 0; kk < 128; ++kk) {
                float4 pv = *(const float4*)&Ps[kk * 64 + ((ty ^ ((kk >> 2) & 7)) << 2)];
                float4 v0 = *(const float4*)&Vs[kk * 128 + tx * 4];
                float4 v1 = *(const float4*)&Vs[kk * 128 + 64 + tx * 4];
                float pf[4] = {pv.x, pv.y, pv.z, pv.w};
#pragma unroll
                for (int i = 0; i < 4; ++i) {
                    o[i][0] = fmaf(pf[i], v0.x, o[i][0]);
                    o[i][1] = fmaf(pf[i], v0.y, o[i][1]);
                    o[i][2] = fmaf(pf[i], v0.z, o[i][2]);
                    o[i][3] = fmaf(pf[i], v0.w, o[i][3]);
                    o[i][4] = fmaf(pf[i], v1.x, o[i][4]);
                    o[i][5] = fmaf(pf[i], v1.y, o[i][5]);
                    o[i][6] = fmaf(pf[i], v1.z, o[i][6]);
                    o[i][7] = fmaf(pf[i], v1.w, o[i][7]);
                }
            }
        }

        // ---- epilogue: normalize and store ----
#pragma unroll
        for (int i = 0; i < 4; ++i) {
            float inv = 1.0f / l_i[i];
            int q = qt * 64 + ty * 4 + i;
            float* op = out + ((size_t)(b * Tt) + q) * Hd;
            float4 r0 = make_float4(o[i][0] * inv, o[i][1] * inv, o[i][2] * inv, o[i][3] * inv);
            float4 r1 = make_float4(o[i][4] * inv, o[i][5] * inv, o[i][6] * inv, o[i][7] * inv);
            *(float4*)&op[tx * 4] = r0;
            *(float4*)&op[64 + tx * 4] = r1;
        }
    }
}

// ---------------------------------------------------------------------------

extern "C" void kernel_launch(void* const* d_in, const int* in_sizes, int n_in,
                              void* d_out, int out_size)
{
    const float* x  = (const float*)d_in[0];
    const float* Wq = (const float*)d_in[1];
    const float* Wk = (const float*)d_in[2];
    const float* Wv = (const float*)d_in[3];
    float* out = (float*)d_out;

    dim3 g1(NROW / 128, 3);
    qkv_kernel<<<g1, 256>>>(x, Wq, Wk, Wv);

    cudaFuncSetAttribute(attn_kernel, cudaFuncAttributeMaxDynamicSharedMemorySize,
                         ATTN_SMEM_BYTES);
    dim3 g2(16, Bb);  // 16 paired q-tile pairs x 8 batches = 128 blocks
    attn_kernel<<<g2, 256, ATTN_SMEM_BYTES>>>(out);
}

// round 9
// speedup vs baseline: 1.6923x; 1.6923x over previous
#include <cuda_runtime.h>
#include <cstdint>
#include <math.h>

#define Bb 8
#define Tt 2048
#define Ee 1024
#define Hd 128
#define NROW (Bb * Tt)

// Scratch (__device__ globals per allocation rules).
__device__ float g_Q[NROW * Hd];
__device__ float g_K[NROW * Hd];
__device__ float g_V[NROW * Hd];

__device__ __forceinline__ float tf32r(float x) {
    float r;
    asm("cvt.rna.tf32.f32 %0, %1;" : "=f"(r) : "f"(x));
    return r;
}

// mma.sync m16n8k8 tf32: D = A*B + C (C==D registers)
__device__ __forceinline__ void mma8(float c[4], uint32_t a0, uint32_t a1,
                                     uint32_t a2, uint32_t a3,
                                     uint32_t b0, uint32_t b1) {
    asm volatile(
        "mma.sync.aligned.m16n8k8.row.col.f32.tf32.tf32.f32 "
        "{%0,%1,%2,%3}, {%4,%5,%6,%7}, {%8,%9}, {%0,%1,%2,%3};"
        : "+f"(c[0]), "+f"(c[1]), "+f"(c[2]), "+f"(c[3])
        : "r"(a0), "r"(a1), "r"(a2), "r"(a3), "r"(b0), "r"(b1));
}

// ===========================================================================
// Kernel 1: QKV projection, fp32 (round-5 proven, ~85% of fp32 peak).
// ===========================================================================
__global__ __launch_bounds__(256, 2) void qkv_kernel(
    const float* __restrict__ x,
    const float* __restrict__ Wq,
    const float* __restrict__ Wk,
    const float* __restrict__ Wv)
{
    __shared__ float As[2][8][128];
    __shared__ float Bs[2][8][128];

    const int which = blockIdx.y;
    const float* __restrict__ W = (which == 0) ? Wq : ((which == 1) ? Wk : Wv);
    float* __restrict__ out = (which == 0) ? g_Q : ((which == 1) ? g_K : g_V);

    const int tid = threadIdx.x;
    const int tx = tid & 15;
    const int ty = tid >> 4;
    const int m0 = blockIdx.x * 128;

    const int arow = tid >> 1;
    const int acol = (tid & 1) * 4;
    const int brow = tid >> 5;
    const int bcol = (tid & 31) * 4;

    const float* xg = x + (size_t)(m0 + arow) * Ee + acol;
    const float* wg = W + (size_t)brow * Hd + bcol;

    float acc[8][8];
#pragma unroll
    for (int i = 0; i < 8; ++i)
#pragma unroll
        for (int j = 0; j < 8; ++j) acc[i][j] = 0.0f;

    {
        float4 a = *(const float4*)xg;
        float4 bv = *(const float4*)wg;
        As[0][acol + 0][arow] = a.x;
        As[0][acol + 1][arow] = a.y;
        As[0][acol + 2][arow] = a.z;
        As[0][acol + 3][arow] = a.w;
        *(float4*)&Bs[0][brow][bcol] = bv;
    }
    __syncthreads();

    int buf = 0;
    const int NT = Ee / 8;
    for (int t = 0; t < NT; ++t) {
        float4 a2, b2;
        if (t < NT - 1) {
            a2 = *(const float4*)(xg + (size_t)(t + 1) * 8);
            b2 = *(const float4*)(wg + (size_t)(t + 1) * 8 * Hd);
        }
#pragma unroll
        for (int k = 0; k < 8; ++k) {
            float4 a0 = *(const float4*)&As[buf][k][ty * 4];
            float4 a1 = *(const float4*)&As[buf][k][64 + ty * 4];
            float4 b0 = *(const float4*)&Bs[buf][k][tx * 4];
            float4 b1 = *(const float4*)&Bs[buf][k][64 + tx * 4];
            float af[8] = {a0.x, a0.y, a0.z, a0.w, a1.x, a1.y, a1.z, a1.w};
            float bf[8] = {b0.x, b0.y, b0.z, b0.w, b1.x, b1.y, b1.z, b1.w};
#pragma unroll
            for (int i = 0; i < 8; ++i)
#pragma unroll
                for (int j = 0; j < 8; ++j)
                    acc[i][j] = fmaf(af[i], bf[j], acc[i][j]);
        }
        if (t < NT - 1) {
            buf ^= 1;
            As[buf][acol + 0][arow] = a2.x;
            As[buf][acol + 1][arow] = a2.y;
            As[buf][acol + 2][arow] = a2.z;
            As[buf][acol + 3][arow] = a2.w;
            *(float4*)&Bs[buf][brow][bcol] = b2;
        }
        __syncthreads();
    }

#pragma unroll
    for (int ih = 0; ih < 2; ++ih) {
#pragma unroll
        for (int i = 0; i < 4; ++i) {
            int row = m0 + ih * 64 + ty * 4 + i;
            float* op = out + (size_t)row * Hd;
            int ii = ih * 4 + i;
            float4 v0 = make_float4(acc[ii][0], acc[ii][1], acc[ii][2], acc[ii][3]);
            float4 v1 = make_float4(acc[ii][4], acc[ii][5], acc[ii][6], acc[ii][7]);
            *(float4*)&op[tx * 4] = v0;
            *(float4*)&op[64 + tx * 4] = v1;
        }
    }
}

// ===========================================================================
// Kernel 2: flash attention on mma.sync tf32 (3x split), fp32 accumulate.
// BQ=64, BK=32, 128 threads (4 warps). Warp w owns q rows [16w,16w+16).
// Pairing (x, 31-x): every CTA runs exactly 66 BK=32 k-tiles.
// ===========================================================================
#define QKSTR 132   // Q/K row stride (floats)
#define VPSTR 36    // V^T / P row stride (floats)

#define SM_QH 0
#define SM_QL (SM_QH + 64 * QKSTR)
#define SM_KH (SM_QL + 64 * QKSTR)
#define SM_KL (SM_KH + 32 * QKSTR)
#define SM_VH (SM_KL + 32 * QKSTR)
#define SM_VL (SM_VH + 128 * VPSTR)
#define SM_PH (SM_VL + 128 * VPSTR)
#define SM_PL (SM_PH + 64 * VPSTR)
#define ATTN_SMEM_FLOATS (SM_PL + 64 * VPSTR)
#define ATTN_SMEM_BYTES (ATTN_SMEM_FLOATS * 4)

__global__ __launch_bounds__(128, 1) void attn_kernel(float* __restrict__ out)
{
    extern __shared__ float sm[];
    float* Qh = sm + SM_QH;
    float* Ql = sm + SM_QL;
    float* Kh = sm + SM_KH;
    float* Kl = sm + SM_KL;
    float* Vh = sm + SM_VH;   // transposed [h][key]
    float* Vl = sm + SM_VL;
    float* Ph = sm + SM_PH;   // [q][key]
    float* Pl = sm + SM_PL;

    const int tid = threadIdx.x;
    const int w = tid >> 5;
    const int lane = tid & 31;
    const int g = lane >> 2;
    const int tig = lane & 3;
    const int b = blockIdx.y;
    const float scale = 45.25483399593904f;  // sqrt(2048)

    const int qrow0 = 16 * w + g;        // local q row for frags (and +8)
    const int aQbase0 = qrow0 * QKSTR;
    const int aQbase1 = (qrow0 + 8) * QKSTR;

    for (int half = 0; half < 2; ++half) {
        const int qt = half ? (31 - (int)blockIdx.x) : (int)blockIdx.x;

        __syncthreads();  // prior half's S-reads of Qh done

        // ---- load Q tile [64][128], split hi/lo ----
        {
            const float* Qg = g_Q + ((size_t)(b * Tt) + qt * 64) * Hd;
#pragma unroll
            for (int it = 0; it < 16; ++it) {
                int fid = it * 128 + tid;
                int r = fid >> 5;
                int c = (fid & 31) << 2;
                float4 v = *(const float4*)&Qg[(size_t)r * Hd + c];
                float4 hi = make_float4(tf32r(v.x), tf32r(v.y), tf32r(v.z), tf32r(v.w));
                float4 lo = make_float4(tf32r(v.x - hi.x), tf32r(v.y - hi.y),
                                        tf32r(v.z - hi.z), tf32r(v.w - hi.w));
                *(float4*)&Qh[r * QKSTR + c] = hi;
                *(float4*)&Ql[r * QKSTR + c] = lo;
            }
        }

        float m0 = -INFINITY, m1 = -INFINITY, l0 = 0.0f, l1 = 0.0f;
        float O[16][4];
#pragma unroll
        for (int a = 0; a < 16; ++a)
#pragma unroll
            for (int j = 0; j < 4; ++j) O[a][j] = 0.0f;

        const int nkt = 2 * qt + 2;
        for (int kt = 0; kt < nkt; ++kt) {
            __syncthreads();  // prev PV done: Kh/Vh reusable

            // ---- load K tile [32][128] (hi/lo) and V tile transposed ----
            {
                const float* Kg = g_K + ((size_t)(b * Tt) + kt * 32) * Hd;
                const float* Vg = g_V + ((size_t)(b * Tt) + kt * 32) * Hd;
#pragma unroll
                for (int it = 0; it < 8; ++it) {
                    int fid = it * 128 + tid;
                    {   // K: coalesced read, row-major store
                        int r = fid >> 5;
                        int c = (fid & 31) << 2;
                        float4 v = *(const float4*)&Kg[(size_t)r * Hd + c];
                        float4 hi = make_float4(tf32r(v.x), tf32r(v.y), tf32r(v.z), tf32r(v.w));
                        float4 lo = make_float4(tf32r(v.x - hi.x), tf32r(v.y - hi.y),
                                                tf32r(v.z - hi.z), tf32r(v.w - hi.w));
                        *(float4*)&Kh[r * QKSTR + c] = hi;
                        *(float4*)&Kl[r * QKSTR + c] = lo;
                    }
                    {   // V: strided read (key varies in-warp), conflict-free transposed store
                        int r = fid & 31;          // key
                        int c = (fid >> 5) << 2;   // h chunk
                        float4 v = *(const float4*)&Vg[(size_t)r * Hd + c];
                        float hv[4] = {v.x, v.y, v.z, v.w};
#pragma unroll
                        for (int j = 0; j < 4; ++j) {
                            float hi = tf32r(hv[j]);
                            Vh[(c + j) * VPSTR + r] = hi;
                            Vl[(c + j) * VPSTR + r] = tf32r(hv[j] - hi);
                        }
                    }
                }
            }
            __syncthreads();

            // ---- S = Q K^T via mma (4 n-atoms of 8 keys), 3 products ----
            float sc[4][4];
#pragma unroll
            for (int a = 0; a < 4; ++a)
#pragma unroll
                for (int j = 0; j < 4; ++j) sc[a][j] = 0.0f;

#pragma unroll
            for (int ks = 0; ks < 16; ++ks) {
                const int kb = ks * 8;
                uint32_t ah0 = __float_as_uint(Qh[aQbase0 + kb + tig]);
                uint32_t ah1 = __float_as_uint(Qh[aQbase1 + kb + tig]);
                uint32_t ah2 = __float_as_uint(Qh[aQbase0 + kb + tig + 4]);
                uint32_t ah3 = __float_as_uint(Qh[aQbase1 + kb + tig + 4]);
                uint32_t al0 = __float_as_uint(Ql[aQbase0 + kb + tig]);
                uint32_t al1 = __float_as_uint(Ql[aQbase1 + kb + tig]);
                uint32_t al2 = __float_as_uint(Ql[aQbase0 + kb + tig + 4]);
                uint32_t al3 = __float_as_uint(Ql[aQbase1 + kb + tig + 4]);
#pragma unroll
                for (int a = 0; a < 4; ++a) {
                    const int kr = (8 * a + g) * QKSTR + kb;
                    uint32_t bh0 = __float_as_uint(Kh[kr + tig]);
                    uint32_t bh1 = __float_as_uint(Kh[kr + tig + 4]);
                    uint32_t bl0 = __float_as_uint(Kl[kr + tig]);
                    uint32_t bl1 = __float_as_uint(Kl[kr + tig + 4]);
                    mma8(sc[a], ah0, ah1, ah2, ah3, bh0, bh1);
                    mma8(sc[a], ah0, ah1, ah2, ah3, bl0, bl1);
                    mma8(sc[a], al0, al1, al2, al3, bh0, bh1);
                }
            }

            // ---- scale + causal mask ----
            const int qg0 = qt * 64 + qrow0;
            const int qg1 = qg0 + 8;
#pragma unroll
            for (int a = 0; a < 4; ++a) {
                const int col = kt * 32 + 8 * a + 2 * tig;
                sc[a][0] = (col     <= qg0) ? sc[a][0] * scale : -INFINITY;
                sc[a][1] = (col + 1 <= qg0) ? sc[a][1] * scale : -INFINITY;
                sc[a][2] = (col     <= qg1) ? sc[a][2] * scale : -INFINITY;
                sc[a][3] = (col + 1 <= qg1) ? sc[a][3] * scale : -INFINITY;
            }

            // ---- row maxima (4-lane groups share a row) ----
            float r0 = fmaxf(fmaxf(sc[0][0], sc[0][1]), fmaxf(sc[1][0], sc[1][1]));
            r0 = fmaxf(r0, fmaxf(fmaxf(sc[2][0], sc[2][1]), fmaxf(sc[3][0], sc[3][1])));
            float r1 = fmaxf(fmaxf(sc[0][2], sc[0][3]), fmaxf(sc[1][2], sc[1][3]));
            r1 = fmaxf(r1, fmaxf(fmaxf(sc[2][2], sc[2][3]), fmaxf(sc[3][2], sc[3][3])));
#pragma unroll
            for (int off = 1; off <= 2; off <<= 1) {
                r0 = fmaxf(r0, __shfl_xor_sync(0xffffffffu, r0, off));
                r1 = fmaxf(r1, __shfl_xor_sync(0xffffffffu, r1, off));
            }

            // exp-skip: contributions below exp(-80) are < 1 ulp of l (~1)
            bool dead = (r0 <= m0 - 80.0f) && (r1 <= m1 - 80.0f);
            if (__all_sync(0xffffffffu, dead)) continue;

            float mn0 = fmaxf(m0, r0);
            float mn1 = fmaxf(m1, r1);
            float al_0 = __expf(m0 - mn0);
            float al_1 = __expf(m1 - mn1);
            float ls0 = 0.0f, ls1 = 0.0f;
#pragma unroll
            for (int a = 0; a < 4; ++a) {
                float p00 = __expf(sc[a][0] - mn0);
                float p01 = __expf(sc[a][1] - mn0);
                float p10 = __expf(sc[a][2] - mn1);
                float p11 = __expf(sc[a][3] - mn1);
                ls0 += p00 + p01;
                ls1 += p10 + p11;
                // store P hi/lo, [q][key], per-warp-private rows
                const int col = 8 * a + 2 * tig;
                float h00 = tf32r(p00), h01 = tf32r(p01);
                float h10 = tf32r(p10), h11 = tf32r(p11);
                Ph[qrow0 * VPSTR + col] = h00;
                Ph[qrow0 * VPSTR + col + 1] = h01;
                Ph[(qrow0 + 8) * VPSTR + col] = h10;
                Ph[(qrow0 + 8) * VPSTR + col + 1] = h11;
                Pl[qrow0 * VPSTR + col] = tf32r(p00 - h00);
                Pl[qrow0 * VPSTR + col + 1] = tf32r(p01 - h01);
                Pl[(qrow0 + 8) * VPSTR + col] = tf32r(p10 - h10);
                Pl[(qrow0 + 8) * VPSTR + col + 1] = tf32r(p11 - h11);
            }
#pragma unroll
            for (int off = 1; off <= 2; off <<= 1) {
                ls0 += __shfl_xor_sync(0xffffffffu, ls0, off);
                ls1 += __shfl_xor_sync(0xffffffffu, ls1, off);
            }
            l0 = l0 * al_0 + ls0;
            l1 = l1 * al_1 + ls1;
            m0 = mn0;
            m1 = mn1;

            // rescale O
#pragma unroll
            for (int a = 0; a < 16; ++a) {
                O[a][0] *= al_0; O[a][1] *= al_0;
                O[a][2] *= al_1; O[a][3] *= al_1;
            }

            __syncwarp();  // P stores visible to the warp's own fragment loads

            // ---- O += P V (16 h-atoms, 4 k-steps, 3 products) ----
#pragma unroll
            for (int ks = 0; ks < 4; ++ks) {
                const int kb = ks * 8;
                uint32_t ah0 = __float_as_uint(Ph[qrow0 * VPSTR + kb + tig]);
                uint32_t ah1 = __float_as_uint(Ph[(qrow0 + 8) * VPSTR + kb + tig]);
                uint32_t ah2 = __float_as_uint(Ph[qrow0 * VPSTR + kb + tig + 4]);
                uint32_t ah3 = __float_as_uint(Ph[(qrow0 + 8) * VPSTR + kb + tig + 4]);
                uint32_t al0 = __float_as_uint(Pl[qrow0 * VPSTR + kb + tig]);
                uint32_t al1 = __float_as_uint(Pl[(qrow0 + 8) * VPSTR + kb + tig]);
                uint32_t al2 = __float_as_uint(Pl[qrow0 * VPSTR + kb + tig + 4]);
                uint32_t al3 = __float_as_uint(Pl[(qrow0 + 8) * VPSTR + kb + tig + 4]);
#pragma unroll
                for (int a = 0; a < 16; ++a) {
                    const int vr = (8 * a + g) * VPSTR + kb;
                    uint32_t bh0 = __float_as_uint(Vh[vr + tig]);
                    uint32_t bh1 = __float_as_uint(Vh[vr + tig + 4]);
                    uint32_t bl0 = __float_as_uint(Vl[vr + tig]);
                    uint32_t bl1 = __float_as_uint(Vl[vr + tig + 4]);
                    mma8(O[a], ah0, ah1, ah2, ah3, bh0, bh1);
                    mma8(O[a], ah0, ah1, ah2, ah3, bl0, bl1);
                    mma8(O[a], al0, al1, al2, al3, bh0, bh1);
                }
            }
        }

        // ---- epilogue ----
        {
            const float inv0 = 1.0f / l0;
            const float inv1 = 1.0f / l1;
            const int q0 = qt * 64 + qrow0;
            float* op0 = out + ((size_t)(b * Tt) + q0) * Hd;
            float* op1 = op0 + 8 * Hd;
#pragma unroll
            for (int a = 0; a < 16; ++a) {
                const int col = 8 * a + 2 * tig;
                float2 v0 = make_float2(O[a][0] * inv0, O[a][1] * inv0);
                float2 v1 = make_float2(O[a][2] * inv1, O[a][3] * inv1);
                *(float2*)&op0[col] = v0;
                *(float2*)&op1[col] = v1;
            }
        }
    }
}

// ===========================================================================

extern "C" void kernel_launch(void* const* d_in, const int* in_sizes, int n_in,
                              void* d_out, int out_size)
{
    const float* x  = (const float*)d_in[0];
    const float* Wq = (const float*)d_in[1];
    const float* Wk = (const float*)d_in[2];
    const float* Wv = (const float*)d_in[3];
    float* out = (float*)d_out;

    dim3 g1(NROW / 128, 3);
    qkv_kernel<<<g1, 256>>>(x, Wq, Wk, Wv);

    cudaFuncSetAttribute(attn_kernel, cudaFuncAttributeMaxDynamicSharedMemorySize,
                         ATTN_SMEM_BYTES);
    dim3 g2(16, Bb);
    attn_kernel<<<g2, 128, ATTN_SMEM_BYTES>>>(out);
}

// round 10
// speedup vs baseline: 1.7871x; 1.0560x over previous
#include <cuda_runtime.h>
#include <cstdint>
#include <math.h>

#define Bb 8
#define Tt 2048
#define Ee 1024
#define Hd 128
#define NROW (Bb * Tt)

// Scratch (__device__ globals per allocation rules).
__device__ float g_Q[NROW * Hd];
__device__ float g_K[NROW * Hd];
__device__ float g_V[NROW * Hd];

__device__ __forceinline__ float tf32r(float x) {
    float r;
    asm("cvt.rna.tf32.f32 %0, %1;" : "=f"(r) : "f"(x));
    return r;
}

// mma.sync m16n8k8 tf32: D = A*B + C (C==D registers)
__device__ __forceinline__ void mma8(float c[4], uint32_t a0, uint32_t a1,
                                     uint32_t a2, uint32_t a3,
                                     uint32_t b0, uint32_t b1) {
    asm volatile(
        "mma.sync.aligned.m16n8k8.row.col.f32.tf32.tf32.f32 "
        "{%0,%1,%2,%3}, {%4,%5,%6,%7}, {%8,%9}, {%0,%1,%2,%3};"
        : "+f"(c[0]), "+f"(c[1]), "+f"(c[2]), "+f"(c[3])
        : "r"(a0), "r"(a1), "r"(a2), "r"(a3), "r"(b0), "r"(b1));
}

// ===========================================================================
// Kernel 1: QKV projection, fp32 (proven, ~58 TF/s).
// ===========================================================================
__global__ __launch_bounds__(256, 2) void qkv_kernel(
    const float* __restrict__ x,
    const float* __restrict__ Wq,
    const float* __restrict__ Wk,
    const float* __restrict__ Wv)
{
    __shared__ float As[2][8][128];
    __shared__ float Bs[2][8][128];

    const int which = blockIdx.y;
    const float* __restrict__ W = (which == 0) ? Wq : ((which == 1) ? Wk : Wv);
    float* __restrict__ out = (which == 0) ? g_Q : ((which == 1) ? g_K : g_V);

    const int tid = threadIdx.x;
    const int tx = tid & 15;
    const int ty = tid >> 4;
    const int m0 = blockIdx.x * 128;

    const int arow = tid >> 1;
    const int acol = (tid & 1) * 4;
    const int brow = tid >> 5;
    const int bcol = (tid & 31) * 4;

    const float* xg = x + (size_t)(m0 + arow) * Ee + acol;
    const float* wg = W + (size_t)brow * Hd + bcol;

    float acc[8][8];
#pragma unroll
    for (int i = 0; i < 8; ++i)
#pragma unroll
        for (int j = 0; j < 8; ++j) acc[i][j] = 0.0f;

    {
        float4 a = *(const float4*)xg;
        float4 bv = *(const float4*)wg;
        As[0][acol + 0][arow] = a.x;
        As[0][acol + 1][arow] = a.y;
        As[0][acol + 2][arow] = a.z;
        As[0][acol + 3][arow] = a.w;
        *(float4*)&Bs[0][brow][bcol] = bv;
    }
    __syncthreads();

    int buf = 0;
    const int NT = Ee / 8;
    for (int t = 0; t < NT; ++t) {
        float4 a2, b2;
        if (t < NT - 1) {
            a2 = *(const float4*)(xg + (size_t)(t + 1) * 8);
            b2 = *(const float4*)(wg + (size_t)(t + 1) * 8 * Hd);
        }
#pragma unroll
        for (int k = 0; k < 8; ++k) {
            float4 a0 = *(const float4*)&As[buf][k][ty * 4];
            float4 a1 = *(const float4*)&As[buf][k][64 + ty * 4];
            float4 b0 = *(const float4*)&Bs[buf][k][tx * 4];
            float4 b1 = *(const float4*)&Bs[buf][k][64 + tx * 4];
            float af[8] = {a0.x, a0.y, a0.z, a0.w, a1.x, a1.y, a1.z, a1.w};
            float bf[8] = {b0.x, b0.y, b0.z, b0.w, b1.x, b1.y, b1.z, b1.w};
#pragma unroll
            for (int i = 0; i < 8; ++i)
#pragma unroll
                for (int j = 0; j < 8; ++j)
                    acc[i][j] = fmaf(af[i], bf[j], acc[i][j]);
        }
        if (t < NT - 1) {
            buf ^= 1;
            As[buf][acol + 0][arow] = a2.x;
            As[buf][acol + 1][arow] = a2.y;
            As[buf][acol + 2][arow] = a2.z;
            As[buf][acol + 3][arow] = a2.w;
            *(float4*)&Bs[buf][brow][bcol] = b2;
        }
        __syncthreads();
    }

#pragma unroll
    for (int ih = 0; ih < 2; ++ih) {
#pragma unroll
        for (int i = 0; i < 4; ++i) {
            int row = m0 + ih * 64 + ty * 4 + i;
            float* op = out + (size_t)row * Hd;
            int ii = ih * 4 + i;
            float4 v0 = make_float4(acc[ii][0], acc[ii][1], acc[ii][2], acc[ii][3]);
            float4 v1 = make_float4(acc[ii][4], acc[ii][5], acc[ii][6], acc[ii][7]);
            *(float4*)&op[tx * 4] = v0;
            *(float4*)&op[64 + tx * 4] = v1;
        }
    }
}

// ===========================================================================
// Kernel 2: flash attention on mma.sync tf32.
// 256 threads = 8 warps = 4 q-groups (16 rows) x 2 key-halves (32 keys).
// BQ=64, BK=64. S uses 3-product tf32 split; PV uses Ph*(Vh+Vl) (2 products).
// Softmax max/sum exchanged across key-halves via smem; partial O summed in
// the epilogue. Pairing (x, 31-x): every CTA runs exactly 33 BK=64 tiles.
// ===========================================================================
#define QKSTR 132   // Q/K row stride (floats)
#define VPSTR 68    // V^T / P row stride (floats)

#define SM_QH 0
#define SM_QL (SM_QH + 64 * QKSTR)          //  8448
#define SM_KH (SM_QL + 64 * QKSTR)          // 16896
#define SM_KL (SM_KH + 64 * QKSTR)          // 25344
#define SM_VH (SM_KL + 64 * QKSTR)          // 33792
#define SM_VL (SM_VH + 128 * VPSTR)         // 42496
#define SM_PH (SM_VL + 128 * VPSTR)         // 51200
#define SM_RMAX (SM_PH + 64 * VPSTR)        // 55552  [2][64]
#define SM_RSUM (SM_RMAX + 128)             // 55680  [2][64]
#define SM_FLAG (SM_RSUM + 128)             // 55808  [4] ints
#define ATTN_SMEM_FLOATS (SM_FLAG + 8)
#define ATTN_SMEM_BYTES (ATTN_SMEM_FLOATS * 4)

__global__ __launch_bounds__(256, 1) void attn_kernel(float* __restrict__ out)
{
    extern __shared__ float sm[];
    float* Qh = sm + SM_QH;
    float* Ql = sm + SM_QL;
    float* Kh = sm + SM_KH;
    float* Kl = sm + SM_KL;
    float* Vh = sm + SM_VH;   // transposed [h][key]
    float* Vl = sm + SM_VL;
    float* Ph = sm + SM_PH;   // [q][key], tf32-rounded hi only
    float* RMAX = sm + SM_RMAX;
    float* RSUM = sm + SM_RSUM;
    int* FLAGS = (int*)(sm + SM_FLAG);

    const int tid = threadIdx.x;
    const int w = tid >> 5;
    const int lane = tid & 31;
    const int g = lane >> 2;
    const int tig = lane & 3;
    const int qgrp = w & 3;
    const int khalf = w >> 2;
    const int kofs = 32 * khalf;
    const int b = blockIdx.y;
    const float scale = 45.25483399593904f;  // sqrt(2048)

    const int qrow0 = 16 * qgrp + g;
    const int aQ0 = qrow0 * QKSTR;
    const int aQ1 = (qrow0 + 8) * QKSTR;

    for (int half = 0; half < 2; ++half) {
        const int qt = half ? (31 - (int)blockIdx.x) : (int)blockIdx.x;

        __syncthreads();  // all smem (incl. epilogue Obuf) reusable

        // ---- load Q tile [64][128], split hi/lo ----
        {
            const float* Qg = g_Q + ((size_t)(b * Tt) + qt * 64) * Hd;
#pragma unroll
            for (int it = 0; it < 8; ++it) {
                int fid = it * 256 + tid;
                int r = fid >> 5;
                int c = (fid & 31) << 2;
                float4 v = *(const float4*)&Qg[(size_t)r * Hd + c];
                float4 hi = make_float4(tf32r(v.x), tf32r(v.y), tf32r(v.z), tf32r(v.w));
                float4 lo = make_float4(tf32r(v.x - hi.x), tf32r(v.y - hi.y),
                                        tf32r(v.z - hi.z), tf32r(v.w - hi.w));
                *(float4*)&Qh[r * QKSTR + c] = hi;
                *(float4*)&Ql[r * QKSTR + c] = lo;
            }
        }

        float m0 = -INFINITY, m1 = -INFINITY, l0 = 0.0f, l1 = 0.0f;
        float O[16][4];
#pragma unroll
        for (int a = 0; a < 16; ++a)
#pragma unroll
            for (int j = 0; j < 4; ++j) O[a][j] = 0.0f;

        for (int kt = 0; kt <= qt; ++kt) {
            __syncthreads();  // prev PV done: K/V/P buffers reusable; Q visible

            // ---- load K tile [64][128] hi/lo and V tile transposed hi/lo ----
            {
                const float* Kg = g_K + ((size_t)(b * Tt) + kt * 64) * Hd;
                const float* Vg = g_V + ((size_t)(b * Tt) + kt * 64) * Hd;
#pragma unroll
                for (int it = 0; it < 8; ++it) {
                    int fid = it * 256 + tid;
                    {   // K: coalesced read, row-major padded store
                        int r = fid >> 5;
                        int c = (fid & 31) << 2;
                        float4 v = *(const float4*)&Kg[(size_t)r * Hd + c];
                        float4 hi = make_float4(tf32r(v.x), tf32r(v.y), tf32r(v.z), tf32r(v.w));
                        float4 lo = make_float4(tf32r(v.x - hi.x), tf32r(v.y - hi.y),
                                                tf32r(v.z - hi.z), tf32r(v.w - hi.w));
                        *(float4*)&Kh[r * QKSTR + c] = hi;
                        *(float4*)&Kl[r * QKSTR + c] = lo;
                    }
                    {   // V: lanes along keys, conflict-free transposed store
                        int r = fid & 63;          // key
                        int c = (fid >> 6) << 2;   // h chunk
                        float4 v = *(const float4*)&Vg[(size_t)r * Hd + c];
                        float hv[4] = {v.x, v.y, v.z, v.w};
#pragma unroll
                        for (int j = 0; j < 4; ++j) {
                            float hi = tf32r(hv[j]);
                            Vh[(c + j) * VPSTR + r] = hi;
                            Vl[(c + j) * VPSTR + r] = tf32r(hv[j] - hi);
                        }
                    }
                }
            }
            __syncthreads();

            // ---- S = Q K^T on this warp's 32-key half (3 products) ----
            float sc[4][4];
#pragma unroll
            for (int a = 0; a < 4; ++a)
#pragma unroll
                for (int j = 0; j < 4; ++j) sc[a][j] = 0.0f;

#pragma unroll
            for (int ks = 0; ks < 16; ++ks) {
                const int kb = ks * 8;
                uint32_t ah0 = __float_as_uint(Qh[aQ0 + kb + tig]);
                uint32_t ah1 = __float_as_uint(Qh[aQ1 + kb + tig]);
                uint32_t ah2 = __float_as_uint(Qh[aQ0 + kb + tig + 4]);
                uint32_t ah3 = __float_as_uint(Qh[aQ1 + kb + tig + 4]);
                uint32_t al0 = __float_as_uint(Ql[aQ0 + kb + tig]);
                uint32_t al1 = __float_as_uint(Ql[aQ1 + kb + tig]);
                uint32_t al2 = __float_as_uint(Ql[aQ0 + kb + tig + 4]);
                uint32_t al3 = __float_as_uint(Ql[aQ1 + kb + tig + 4]);
#pragma unroll
                for (int a = 0; a < 4; ++a) {
                    const int kr = (kofs + 8 * a + g) * QKSTR + kb;
                    uint32_t bh0 = __float_as_uint(Kh[kr + tig]);
                    uint32_t bh1 = __float_as_uint(Kh[kr + tig + 4]);
                    uint32_t bl0 = __float_as_uint(Kl[kr + tig]);
                    uint32_t bl1 = __float_as_uint(Kl[kr + tig + 4]);
                    mma8(sc[a], ah0, ah1, ah2, ah3, bh0, bh1);
                    mma8(sc[a], ah0, ah1, ah2, ah3, bl0, bl1);
                    mma8(sc[a], al0, al1, al2, al3, bh0, bh1);
                }
            }

            // ---- scale + causal mask ----
            const int qg0 = qt * 64 + qrow0;
            const int qg1 = qg0 + 8;
#pragma unroll
            for (int a = 0; a < 4; ++a) {
                const int col = kt * 64 + kofs + 8 * a + 2 * tig;
                sc[a][0] = (col     <= qg0) ? sc[a][0] * scale : -INFINITY;
                sc[a][1] = (col + 1 <= qg0) ? sc[a][1] * scale : -INFINITY;
                sc[a][2] = (col     <= qg1) ? sc[a][2] * scale : -INFINITY;
                sc[a][3] = (col + 1 <= qg1) ? sc[a][3] * scale : -INFINITY;
            }

            // ---- local row maxima (4-lane groups) ----
            float r0 = fmaxf(fmaxf(sc[0][0], sc[0][1]), fmaxf(sc[1][0], sc[1][1]));
            r0 = fmaxf(r0, fmaxf(fmaxf(sc[2][0], sc[2][1]), fmaxf(sc[3][0], sc[3][1])));
            float r1 = fmaxf(fmaxf(sc[0][2], sc[0][3]), fmaxf(sc[1][2], sc[1][3]));
            r1 = fmaxf(r1, fmaxf(fmaxf(sc[2][2], sc[2][3]), fmaxf(sc[3][2], sc[3][3])));
#pragma unroll
            for (int off = 1; off <= 2; off <<= 1) {
                r0 = fmaxf(r0, __shfl_xor_sync(0xffffffffu, r0, off));
                r1 = fmaxf(r1, __shfl_xor_sync(0xffffffffu, r1, off));
            }
            if (tig == 0) {
                RMAX[khalf * 64 + qrow0] = r0;
                RMAX[khalf * 64 + qrow0 + 8] = r1;
            }
            __syncthreads();

            // ---- combined maxima across key-halves; CTA-uniform dead skip ----
            float cm0 = fmaxf(RMAX[qrow0], RMAX[64 + qrow0]);
            float cm1 = fmaxf(RMAX[qrow0 + 8], RMAX[64 + qrow0 + 8]);
            bool dead = (cm0 <= m0 - 80.0f) && (cm1 <= m1 - 80.0f);
            unsigned wd = __all_sync(0xffffffffu, dead);
            if (khalf == 0 && lane == 0) FLAGS[qgrp] = (int)wd;
            __syncthreads();
            if (FLAGS[0] & FLAGS[1] & FLAGS[2] & FLAGS[3]) continue;

            float mn0 = fmaxf(m0, cm0);
            float mn1 = fmaxf(m1, cm1);
            float al_0 = __expf(m0 - mn0);
            float al_1 = __expf(m1 - mn1);
            float ls0 = 0.0f, ls1 = 0.0f;
#pragma unroll
            for (int a = 0; a < 4; ++a) {
                float p00 = __expf(sc[a][0] - mn0);
                float p01 = __expf(sc[a][1] - mn0);
                float p10 = __expf(sc[a][2] - mn1);
                float p11 = __expf(sc[a][3] - mn1);
                ls0 += p00 + p01;
                ls1 += p10 + p11;
                const int col = kofs + 8 * a + 2 * tig;
                Ph[qrow0 * VPSTR + col] = tf32r(p00);
                Ph[qrow0 * VPSTR + col + 1] = tf32r(p01);
                Ph[(qrow0 + 8) * VPSTR + col] = tf32r(p10);
                Ph[(qrow0 + 8) * VPSTR + col + 1] = tf32r(p11);
            }
#pragma unroll
            for (int off = 1; off <= 2; off <<= 1) {
                ls0 += __shfl_xor_sync(0xffffffffu, ls0, off);
                ls1 += __shfl_xor_sync(0xffffffffu, ls1, off);
            }
            if (tig == 0) {
                RSUM[khalf * 64 + qrow0] = ls0;
                RSUM[khalf * 64 + qrow0 + 8] = ls1;
            }
            __syncthreads();   // P and RSUM visible to all

            l0 = l0 * al_0 + RSUM[qrow0] + RSUM[64 + qrow0];
            l1 = l1 * al_1 + RSUM[qrow0 + 8] + RSUM[64 + qrow0 + 8];
            m0 = mn0;
            m1 = mn1;

#pragma unroll
            for (int a = 0; a < 16; ++a) {
                O[a][0] *= al_0; O[a][1] *= al_0;
                O[a][2] *= al_1; O[a][3] *= al_1;
            }

            // ---- O_partial += P(:, this key-half) V(this key-half, :) ----
#pragma unroll
            for (int ks = 0; ks < 4; ++ks) {
                const int kb = kofs + ks * 8;
                uint32_t a0 = __float_as_uint(Ph[qrow0 * VPSTR + kb + tig]);
                uint32_t a1 = __float_as_uint(Ph[(qrow0 + 8) * VPSTR + kb + tig]);
                uint32_t a2 = __float_as_uint(Ph[qrow0 * VPSTR + kb + tig + 4]);
                uint32_t a3 = __float_as_uint(Ph[(qrow0 + 8) * VPSTR + kb + tig + 4]);
#pragma unroll
                for (int a = 0; a < 16; ++a) {
                    const int vr = (8 * a + g) * VPSTR + kb;
                    uint32_t bh0 = __float_as_uint(Vh[vr + tig]);
                    uint32_t bh1 = __float_as_uint(Vh[vr + tig + 4]);
                    uint32_t bl0 = __float_as_uint(Vl[vr + tig]);
                    uint32_t bl1 = __float_as_uint(Vl[vr + tig + 4]);
                    mma8(O[a], a0, a1, a2, a3, bh0, bh1);
                    mma8(O[a], a0, a1, a2, a3, bl0, bl1);
                }
            }
        }

        // ---- epilogue: sum the two key-half partial O's, normalize, store ----
        __syncthreads();           // mainloop reads of Kh done
        float* Obuf = Kh;          // reuse [64][132]
        if (khalf == 1) {
#pragma unroll
            for (int a = 0; a < 16; ++a) {
                const int colc = 8 * a + 2 * tig;
                *(float2*)&Obuf[qrow0 * QKSTR + colc] = make_float2(O[a][0], O[a][1]);
                *(float2*)&Obuf[(qrow0 + 8) * QKSTR + colc] = make_float2(O[a][2], O[a][3]);
            }
        }
        __syncthreads();
        if (khalf == 0) {
            const float inv0 = 1.0f / l0;
            const float inv1 = 1.0f / l1;
            const int q0 = qt * 64 + qrow0;
            float* op0 = out + ((size_t)(b * Tt) + q0) * Hd;
            float* op1 = op0 + 8 * Hd;
#pragma unroll
            for (int a = 0; a < 16; ++a) {
                const int colc = 8 * a + 2 * tig;
                float2 e0 = *(float2*)&Obuf[qrow0 * QKSTR + colc];
                float2 e1 = *(float2*)&Obuf[(qrow0 + 8) * QKSTR + colc];
                *(float2*)&op0[colc] =
                    make_float2((O[a][0] + e0.x) * inv0, (O[a][1] + e0.y) * inv0);
                *(float2*)&op1[colc] =
                    make_float2((O[a][2] + e1.x) * inv1, (O[a][3] + e1.y) * inv1);
            }
        }
    }
}

// ===========================================================================

extern "C" void kernel_launch(void* const* d_in, const int* in_sizes, int n_in,
                              void* d_out, int out_size)
{
    const float* x  = (const float*)d_in[0];
    const float* Wq = (const float*)d_in[1];
    const float* Wk = (const float*)d_in[2];
    const float* Wv = (const float*)d_in[3];
    float* out = (float*)d_out;

    dim3 g1(NROW / 128, 3);
    qkv_kernel<<<g1, 256>>>(x, Wq, Wk, Wv);

    cudaFuncSetAttribute(attn_kernel, cudaFuncAttributeMaxDynamicSharedMemorySize,
                         ATTN_SMEM_BYTES);
    dim3 g2(16, Bb);
    attn_kernel<<<g2, 256, ATTN_SMEM_BYTES>>>(out);
}

// round 12
// speedup vs baseline: 1.8881x; 1.0565x over previous
#include <cuda_runtime.h>
#include <cstdint>
#include <math.h>

#define Bb 8
#define Tt 2048
#define Ee 1024
#define Hd 128
#define NROW (Bb * Tt)

// Scratch (__device__ globals per allocation rules).
__device__ float g_Q[NROW * Hd];
__device__ float g_K[NROW * Hd];
__device__ float g_V[NROW * Hd];

__device__ __forceinline__ float tf32r(float x) {
    float r;
    asm("cvt.rna.tf32.f32 %0, %1;" : "=f"(r) : "f"(x));
    return r;
}

// mma.sync m16n8k8 tf32: D = A*B + C (C==D registers)
__device__ __forceinline__ void mma8(float c[4], uint32_t a0, uint32_t a1,
                                     uint32_t a2, uint32_t a3,
                                     uint32_t b0, uint32_t b1) {
    asm volatile(
        "mma.sync.aligned.m16n8k8.row.col.f32.tf32.tf32.f32 "
        "{%0,%1,%2,%3}, {%4,%5,%6,%7}, {%8,%9}, {%0,%1,%2,%3};"
        : "+f"(c[0]), "+f"(c[1]), "+f"(c[2]), "+f"(c[3])
        : "r"(a0), "r"(a1), "r"(a2), "r"(a3), "r"(b0), "r"(b1));
}

// ===========================================================================
// Kernel 1: QKV projection, fp32 (proven ~85% of fp32 peak; tensor-core
// alternative is NOT faster here: mma.sync tf32 3-product split needs
// >=163us at 100% tensor on this chip's measured mma rate).
// ===========================================================================
__global__ __launch_bounds__(256, 2) void qkv_kernel(
    const float* __restrict__ x,
    const float* __restrict__ Wq,
    const float* __restrict__ Wk,
    const float* __restrict__ Wv)
{
    __shared__ float As[2][8][128];
    __shared__ float Bs[2][8][128];

    const int which = blockIdx.y;
    const float* __restrict__ W = (which == 0) ? Wq : ((which == 1) ? Wk : Wv);
    float* __restrict__ out = (which == 0) ? g_Q : ((which == 1) ? g_K : g_V);

    const int tid = threadIdx.x;
    const int tx = tid & 15;
    const int ty = tid >> 4;
    const int m0 = blockIdx.x * 128;

    const int arow = tid >> 1;
    const int acol = (tid & 1) * 4;
    const int brow = tid >> 5;
    const int bcol = (tid & 31) * 4;

    const float* xg = x + (size_t)(m0 + arow) * Ee + acol;
    const float* wg = W + (size_t)brow * Hd + bcol;

    float acc[8][8];
#pragma unroll
    for (int i = 0; i < 8; ++i)
#pragma unroll
        for (int j = 0; j < 8; ++j) acc[i][j] = 0.0f;

    {
        float4 a = *(const float4*)xg;
        float4 bv = *(const float4*)wg;
        As[0][acol + 0][arow] = a.x;
        As[0][acol + 1][arow] = a.y;
        As[0][acol + 2][arow] = a.z;
        As[0][acol + 3][arow] = a.w;
        *(float4*)&Bs[0][brow][bcol] = bv;
    }
    __syncthreads();

    int buf = 0;
    const int NT = Ee / 8;
    for (int t = 0; t < NT; ++t) {
        float4 a2, b2;
        if (t < NT - 1) {
            a2 = *(const float4*)(xg + (size_t)(t + 1) * 8);
            b2 = *(const float4*)(wg + (size_t)(t + 1) * 8 * Hd);
        }
#pragma unroll
        for (int k = 0; k < 8; ++k) {
            float4 a0 = *(const float4*)&As[buf][k][ty * 4];
            float4 a1 = *(const float4*)&As[buf][k][64 + ty * 4];
            float4 b0 = *(const float4*)&Bs[buf][k][tx * 4];
            float4 b1 = *(const float4*)&Bs[buf][k][64 + tx * 4];
            float af[8] = {a0.x, a0.y, a0.z, a0.w, a1.x, a1.y, a1.z, a1.w};
            float bf[8] = {b0.x, b0.y, b0.z, b0.w, b1.x, b1.y, b1.z, b1.w};
#pragma unroll
            for (int i = 0; i < 8; ++i)
#pragma unroll
                for (int j = 0; j < 8; ++j)
                    acc[i][j] = fmaf(af[i], bf[j], acc[i][j]);
        }
        if (t < NT - 1) {
            buf ^= 1;
            As[buf][acol + 0][arow] = a2.x;
            As[buf][acol + 1][arow] = a2.y;
            As[buf][acol + 2][arow] = a2.z;
            As[buf][acol + 3][arow] = a2.w;
            *(float4*)&Bs[buf][brow][bcol] = b2;
        }
        __syncthreads();
    }

#pragma unroll
    for (int ih = 0; ih < 2; ++ih) {
#pragma unroll
        for (int i = 0; i < 4; ++i) {
            int row = m0 + ih * 64 + ty * 4 + i;
            float* op = out + (size_t)row * Hd;
            int ii = ih * 4 + i;
            float4 v0 = make_float4(acc[ii][0], acc[ii][1], acc[ii][2], acc[ii][3]);
            float4 v1 = make_float4(acc[ii][4], acc[ii][5], acc[ii][6], acc[ii][7]);
            *(float4*)&op[tx * 4] = v0;
            *(float4*)&op[64 + tx * 4] = v1;
        }
    }
}

// ===========================================================================
// Kernel 2: flash attention on mma.sync tf32.
// 256 threads = 8 warps = 4 q-groups (16 rows) x 2 key-halves (32 keys).
// Each key-half keeps an INDEPENDENT online softmax (m,l,O); the two halves
// merge once per q-tile in the epilogue (split-KV merge). Only 2 syncthreads
// per tile. PV uses Ph*Vh only. Pairing (x, 31-x): 33 BK=64 tiles per CTA.
// ===========================================================================
#define QKSTR 132   // Q/K row stride (floats)
#define VPSTR 68    // V^T / P row stride (floats)

#define SM_QH 0
#define SM_QL (SM_QH + 64 * QKSTR)
#define SM_KH (SM_QL + 64 * QKSTR)
#define SM_KL (SM_KH + 64 * QKSTR)
#define SM_VH (SM_KL + 64 * QKSTR)
#define SM_PH (SM_VH + 128 * VPSTR)
#define SM_MM (SM_PH + 64 * VPSTR)
#define SM_LL (SM_MM + 64)
#define ATTN_SMEM_FLOATS (SM_LL + 64)
#define ATTN_SMEM_BYTES (ATTN_SMEM_FLOATS * 4)

__global__ __launch_bounds__(256, 1) void attn_kernel(float* __restrict__ out)
{
    extern __shared__ float sm[];
    float* Qh = sm + SM_QH;
    float* Ql = sm + SM_QL;
    float* Kh = sm + SM_KH;
    float* Kl = sm + SM_KL;
    float* Vh = sm + SM_VH;   // transposed [h][key]
    float* Ph = sm + SM_PH;   // [q][key], tf32-rounded
    float* MM = sm + SM_MM;
    float* LL = sm + SM_LL;

    const int tid = threadIdx.x;
    const int w = tid >> 5;
    const int lane = tid & 31;
    const int g = lane >> 2;
    const int tig = lane & 3;
    const int qgrp = w & 3;
    const int khalf = w >> 2;
    const int kofs = 32 * khalf;
    const int b = blockIdx.y;
    const float scale = 45.25483399593904f;  // sqrt(2048)

    const int qrow0 = 16 * qgrp + g;
    const int aQ0 = qrow0 * QKSTR;
    const int aQ1 = (qrow0 + 8) * QKSTR;

    for (int half = 0; half < 2; ++half) {
        const int qt = half ? (31 - (int)blockIdx.x) : (int)blockIdx.x;

        __syncthreads();  // all smem (incl. epilogue buffers) reusable

        // ---- load Q tile [64][128], split hi/lo ----
        {
            const float* Qg = g_Q + ((size_t)(b * Tt) + qt * 64) * Hd;
#pragma unroll
            for (int it = 0; it < 8; ++it) {
                int fid = it * 256 + tid;
                int r = fid >> 5;
                int c = (fid & 31) << 2;
                float4 v = *(const float4*)&Qg[(size_t)r * Hd + c];
                float4 hi = make_float4(tf32r(v.x), tf32r(v.y), tf32r(v.z), tf32r(v.w));
                float4 lo = make_float4(tf32r(v.x - hi.x), tf32r(v.y - hi.y),
                                        tf32r(v.z - hi.z), tf32r(v.w - hi.w));
                *(float4*)&Qh[r * QKSTR + c] = hi;
                *(float4*)&Ql[r * QKSTR + c] = lo;
            }
        }

        float m0 = -INFINITY, m1 = -INFINITY, l0 = 0.0f, l1 = 0.0f;
        float O[16][4];
#pragma unroll
        for (int a = 0; a < 16; ++a)
#pragma unroll
            for (int j = 0; j < 4; ++j) O[a][j] = 0.0f;

        for (int kt = 0; kt <= qt; ++kt) {
            __syncthreads();  // prev compute done: K/V buffers reusable; Q visible

            // ---- load K tile [64][128] hi/lo and V tile transposed (hi only) ----
            {
                const float* Kg = g_K + ((size_t)(b * Tt) + kt * 64) * Hd;
                const float* Vg = g_V + ((size_t)(b * Tt) + kt * 64) * Hd;
#pragma unroll
                for (int it = 0; it < 8; ++it) {
                    int fid = it * 256 + tid;
                    {   // K: coalesced read, row-major padded store
                        int r = fid >> 5;
                        int c = (fid & 31) << 2;
                        float4 v = *(const float4*)&Kg[(size_t)r * Hd + c];
                        float4 hi = make_float4(tf32r(v.x), tf32r(v.y), tf32r(v.z), tf32r(v.w));
                        float4 lo = make_float4(tf32r(v.x - hi.x), tf32r(v.y - hi.y),
                                                tf32r(v.z - hi.z), tf32r(v.w - hi.w));
                        *(float4*)&Kh[r * QKSTR + c] = hi;
                        *(float4*)&Kl[r * QKSTR + c] = lo;
                    }
                    {   // V: transposed store, tf32 hi only
                        int r = fid & 63;          // key
                        int c = (fid >> 6) << 2;   // h chunk
                        float4 v = *(const float4*)&Vg[(size_t)r * Hd + c];
                        Vh[(c + 0) * VPSTR + r] = tf32r(v.x);
                        Vh[(c + 1) * VPSTR + r] = tf32r(v.y);
                        Vh[(c + 2) * VPSTR + r] = tf32r(v.z);
                        Vh[(c + 3) * VPSTR + r] = tf32r(v.w);
                    }
                }
            }
            __syncthreads();

            // ---- S = Q K^T on this warp's 32-key half (3 products) ----
            float sc[4][4];
#pragma unroll
            for (int a = 0; a < 4; ++a)
#pragma unroll
                for (int j = 0; j < 4; ++j) sc[a][j] = 0.0f;

#pragma unroll
            for (int ks = 0; ks < 16; ++ks) {
                const int kb = ks * 8;
                uint32_t ah0 = __float_as_uint(Qh[aQ0 + kb + tig]);
                uint32_t ah1 = __float_as_uint(Qh[aQ1 + kb + tig]);
                uint32_t ah2 = __float_as_uint(Qh[aQ0 + kb + tig + 4]);
                uint32_t ah3 = __float_as_uint(Qh[aQ1 + kb + tig + 4]);
                uint32_t al0 = __float_as_uint(Ql[aQ0 + kb + tig]);
                uint32_t al1 = __float_as_uint(Ql[aQ1 + kb + tig]);
                uint32_t al2 = __float_as_uint(Ql[aQ0 + kb + tig + 4]);
                uint32_t al3 = __float_as_uint(Ql[aQ1 + kb + tig + 4]);
#pragma unroll
                for (int a = 0; a < 4; ++a) {
                    const int kr = (kofs + 8 * a + g) * QKSTR + kb;
                    uint32_t bh0 = __float_as_uint(Kh[kr + tig]);
                    uint32_t bh1 = __float_as_uint(Kh[kr + tig + 4]);
                    uint32_t bl0 = __float_as_uint(Kl[kr + tig]);
                    uint32_t bl1 = __float_as_uint(Kl[kr + tig + 4]);
                    mma8(sc[a], ah0, ah1, ah2, ah3, bh0, bh1);
                    mma8(sc[a], ah0, ah1, ah2, ah3, bl0, bl1);
                    mma8(sc[a], al0, al1, al2, al3, bh0, bh1);
                }
            }

            // ---- scale + causal mask ----
            const int qg0 = qt * 64 + qrow0;
            const int qg1 = qg0 + 8;
#pragma unroll
            for (int a = 0; a < 4; ++a) {
                const int col = kt * 64 + kofs + 8 * a + 2 * tig;
                sc[a][0] = (col     <= qg0) ? sc[a][0] * scale : -INFINITY;
                sc[a][1] = (col + 1 <= qg0) ? sc[a][1] * scale : -INFINITY;
                sc[a][2] = (col     <= qg1) ? sc[a][2] * scale : -INFINITY;
                sc[a][3] = (col + 1 <= qg1) ? sc[a][3] * scale : -INFINITY;
            }

            // ---- row maxima over this half (4-lane groups) ----
            float r0 = fmaxf(fmaxf(sc[0][0], sc[0][1]), fmaxf(sc[1][0], sc[1][1]));
            r0 = fmaxf(r0, fmaxf(fmaxf(sc[2][0], sc[2][1]), fmaxf(sc[3][0], sc[3][1])));
            float r1 = fmaxf(fmaxf(sc[0][2], sc[0][3]), fmaxf(sc[1][2], sc[1][3]));
            r1 = fmaxf(r1, fmaxf(fmaxf(sc[2][2], sc[2][3]), fmaxf(sc[3][2], sc[3][3])));
#pragma unroll
            for (int off = 1; off <= 2; off <<= 1) {
                r0 = fmaxf(r0, __shfl_xor_sync(0xffffffffu, r0, off));
                r1 = fmaxf(r1, __shfl_xor_sync(0xffffffffu, r1, off));
            }

            // ---- warp-local dead skip (contributions < e^-80 of final l) ----
            bool dead = (r0 <= m0 - 80.0f) && (r1 <= m1 - 80.0f);
            if (__all_sync(0xffffffffu, dead)) continue;

            // clamp so fully-masked rows never produce -inf - -inf = NaN
            float mn0 = fmaxf(fmaxf(m0, r0), -1e30f);
            float mn1 = fmaxf(fmaxf(m1, r1), -1e30f);
            float al_0 = __expf(m0 - mn0);
            float al_1 = __expf(m1 - mn1);
            float ls0 = 0.0f, ls1 = 0.0f;
#pragma unroll
            for (int a = 0; a < 4; ++a) {
                float p00 = __expf(sc[a][0] - mn0);
                float p01 = __expf(sc[a][1] - mn0);
                float p10 = __expf(sc[a][2] - mn1);
                float p11 = __expf(sc[a][3] - mn1);
                ls0 += p00 + p01;
                ls1 += p10 + p11;
                const int col = kofs + 8 * a + 2 * tig;
                Ph[qrow0 * VPSTR + col] = tf32r(p00);
                Ph[qrow0 * VPSTR + col + 1] = tf32r(p01);
                Ph[(qrow0 + 8) * VPSTR + col] = tf32r(p10);
                Ph[(qrow0 + 8) * VPSTR + col + 1] = tf32r(p11);
            }
#pragma unroll
            for (int off = 1; off <= 2; off <<= 1) {
                ls0 += __shfl_xor_sync(0xffffffffu, ls0, off);
                ls1 += __shfl_xor_sync(0xffffffffu, ls1, off);
            }
            l0 = l0 * al_0 + ls0;
            l1 = l1 * al_1 + ls1;
            m0 = mn0;
            m1 = mn1;

#pragma unroll
            for (int a = 0; a < 16; ++a) {
                O[a][0] *= al_0; O[a][1] *= al_0;
                O[a][2] *= al_1; O[a][3] *= al_1;
            }

            __syncwarp();  // P block is warp-private; order STS before LDS

            // ---- O_half += P(:, half) V(half, :)  (hi product only) ----
#pragma unroll
            for (int ks = 0; ks < 4; ++ks) {
                const int kb = kofs + ks * 8;
                uint32_t a0 = __float_as_uint(Ph[qrow0 * VPSTR + kb + tig]);
                uint32_t a1 = __float_as_uint(Ph[(qrow0 + 8) * VPSTR + kb + tig]);
                uint32_t a2 = __float_as_uint(Ph[qrow0 * VPSTR + kb + tig + 4]);
                uint32_t a3 = __float_as_uint(Ph[(qrow0 + 8) * VPSTR + kb + tig + 4]);
#pragma unroll
                for (int a = 0; a < 16; ++a) {
                    const int vr = (8 * a + g) * VPSTR + kb;
                    uint32_t bh0 = __float_as_uint(Vh[vr + tig]);
                    uint32_t bh1 = __float_as_uint(Vh[vr + tig + 4]);
                    mma8(O[a], a0, a1, a2, a3, bh0, bh1);
                }
            }
        }

        // ---- epilogue: split-KV merge of the two key-halves ----
        __syncthreads();           // mainloop reads of Kh done
        float* Obuf = Kh;          // reuse [64][132]
        if (khalf == 1) {
#pragma unroll
            for (int a = 0; a < 16; ++a) {
                const int colc = 8 * a + 2 * tig;
                *(float2*)&Obuf[qrow0 * QKSTR + colc] = make_float2(O[a][0], O[a][1]);
                *(float2*)&Obuf[(qrow0 + 8) * QKSTR + colc] = make_float2(O[a][2], O[a][3]);
            }
            if (tig == 0) {
                MM[qrow0] = m0; LL[qrow0] = l0;
                MM[qrow0 + 8] = m1; LL[qrow0 + 8] = l1;
            }
        }
        __syncthreads();
        if (khalf == 0) {
            const float m1r = MM[qrow0],     l1r = LL[qrow0];
            const float m3r = MM[qrow0 + 8], l3r = LL[qrow0 + 8];
            const float mf0 = fmaxf(m0, m1r);
            const float mf1 = fmaxf(m1, m3r);
            const float w00 = __expf(m0 - mf0), w01 = __expf(m1r - mf0);
            const float w10 = __expf(m1 - mf1), w11 = __expf(m3r - mf1);
            const float inv0 = 1.0f / (l0 * w00 + l1r * w01);
            const float inv1 = 1.0f / (l1 * w10 + l3r * w11);
            const int q0 = qt * 64 + qrow0;
            float* op0 = out + ((size_t)(b * Tt) + q0) * Hd;
            float* op1 = op0 + 8 * Hd;
#pragma unroll
            for (int a = 0; a < 16; ++a) {
                const int colc = 8 * a + 2 * tig;
                float2 e0 = *(float2*)&Obuf[qrow0 * QKSTR + colc];
                float2 e1 = *(float2*)&Obuf[(qrow0 + 8) * QKSTR + colc];
                *(float2*)&op0[colc] =
                    make_float2((O[a][0] * w00 + e0.x * w01) * inv0,
                                (O[a][1] * w00 + e0.y * w01) * inv0);
                *(float2*)&op1[colc] =
                    make_float2((O[a][2] * w10 + e1.x * w11) * inv1,
                                (O[a][3] * w10 + e1.y * w11) * inv1);
            }
        }
    }
}

// ===========================================================================

extern "C" void kernel_launch(void* const* d_in, const int* in_sizes, int n_in,
                              void* d_out, int out_size)
{
    const float* x  = (const float*)d_in[0];
    const float* Wq = (const float*)d_in[1];
    const float* Wk = (const float*)d_in[2];
    const float* Wv = (const float*)d_in[3];
    float* out = (float*)d_out;

    dim3 g1(NROW / 128, 3);
    qkv_kernel<<<g1, 256>>>(x, Wq, Wk, Wv);

    cudaFuncSetAttribute(attn_kernel, cudaFuncAttributeMaxDynamicSharedMemorySize,
                         ATTN_SMEM_BYTES);
    dim3 g2(16, Bb);
    attn_kernel<<<g2, 256, ATTN_SMEM_BYTES>>>(out);
}